// round 17
// baseline (speedup 1.0000x reference)
#include <cuda_runtime.h>
#include <cuda_fp16.h>
#include <cstdint>

// Problem constants (fixed shapes per reference)
#define C_    64
#define D_    8
#define K15_  15
#define K16_  16
#define OUTW  512
#define MAXB  32768
#define NJT   8               // j-tiles of 64
#define ROWB  128             // 64 j fp16 per row
#define TROWS 1024            // c*16+e rows per tile
#define TILEB (TROWS * ROWB)  // 131072 B: one jt tile, smem-resident
#define GCH   128             // b per chunk
#define GY    18              // gather rounds stride
#define NCTA  144             // 8 jt x 18, one co-resident wave
#define MAXCH (MAXB / GCH)    // 256 chunks

// Scratch (no cudaMalloc allowed): zero-initialized device globals.
__device__ uint8_t        g_table[1 << K15_];   // sign pattern -> argmax_j
__device__ unsigned short g_poff[MAXB * C_];    // (b,c) -> e*128 (row byte off)
__device__ unsigned       g_tcnt, g_tdone;      // table flag (produce/consume counters)
__device__ unsigned       g_cflag[MAXCH];       // chunk ready flags
__device__ unsigned       g_cdone[MAXCH];       // chunk consume counters (8 each)

__device__ __forceinline__ void cp16(uint32_t daddr, const void* src) {
    asm volatile("cp.async.cg.shared.global [%0], [%1], 16;" :: "r"(daddr), "l"(src) : "memory");
}

// ---------------------------------------------------------------------------
// smem layout (dynamic, 165 KB):
//   [0, 32768)      idx phase: S_s ([c][d][16] f32) | gather phase: id bufs 2x16KB
//   [32768, ...)    T_s (960 f32)
//   [36608, ...)    Hs (240 f32)
//   [37888, +128K)  jt tile (fp16, 1024 rows x 128 B)
// ---------------------------------------------------------------------------
#define IDB0   0u
#define IDB1   16384u
#define TS_OFF 32768
#define HS_OFF 36608
#define TOFF   37888u
#define GSMEM  (TOFF + TILEB)

__global__ void __launch_bounds__(1024, 1) fused_kernel(const float* __restrict__ x,
                                                        const float* __restrict__ S,
                                                        const float* __restrict__ T,
                                                        const float* __restrict__ H,
                                                        const float* __restrict__ LUT,
                                                        float* __restrict__ out, int B) {
    extern __shared__ char smem[];
    float* S_s = (float*)smem;
    float* T_s = (float*)(smem + TS_OFF);
    float* Hs  = (float*)(smem + HS_OFF);

    const int tid = threadIdx.x, w = tid >> 5, lane = tid & 31;
    const int bid = blockIdx.x;
    const int jt = bid & 7, y = bid >> 3;
    const uint32_t sb = (uint32_t)__cvta_generic_to_shared(smem);
    const int nch = (B + GCH - 1) / GCH;

    // ================= stage A: staging =================
    if (tid < K15_ * K16_) Hs[tid] = H[tid];
    for (int i = tid; i < C_ * K15_; i += 1024) T_s[i] = T[i];
    for (int i = tid; i < C_ * D_ * K15_; i += 1024) {
        int cd = i / K15_, k = i - cd * K15_;
        S_s[cd * 16 + k] = S[i];
    }
    __syncthreads();

    // ================= table: 32 producer CTAs, counter flag =================
    if (bid < 32) {
        const int m = bid * 1024 + tid;
        float h[K16_];
#pragma unroll
        for (int j = 0; j < K16_; j++) h[j] = 0.f;
#pragma unroll
        for (int k = 0; k < K15_; k++) {
            float sgn = ((m >> k) & 1) ? 1.f : -1.f;
#pragma unroll
            for (int j = 0; j < K16_; j++) h[j] += sgn * Hs[k * K16_ + j];
        }
        float best = h[0];
        int   bi = 0;
#pragma unroll
        for (int j = 1; j < K16_; j++)
            if (h[j] > best) { best = h[j]; bi = j; }
        g_table[m] = (uint8_t)bi;
        __threadfence();
        __syncthreads();
        if (tid == 0) atomicAdd(&g_tcnt, 1u);
    }
    // consume table flag (replay-safe: last of 144 consumers resets)
    if (tid == 0) {
        while (*(volatile unsigned*)&g_tcnt < 32u) {}
        __threadfence();
        const unsigned old = atomicAdd(&g_tdone, 1u);
        if (old == NCTA - 1) { g_tdone = 0u; g_tcnt = 0u; }
    }
    __syncthreads();

    // ================= stage B: idx for my chunks (split-k, <=64 regs) =======
    for (int ch = bid; ch < nch; ch += NCTA) {
        const int bg = ch * 4 + (w >> 3);    // 4 b-groups per chunk
        const int cg = w & 7;
        const int b = bg * 32 + lane;
        const float* xrow = x + (size_t)((b < B) ? b : 0) * 512;

        int e8[8];
#pragma unroll
        for (int cc = 0; cc < 8; cc++) {
            const int c = cg * 8 + cc;
            const float4 xa = __ldg((const float4*)(xrow + c * 8));
            const float4 xb = __ldg((const float4*)(xrow + c * 8 + 4));
            unsigned m = 0;
            {   // k = 0..7
                float acc[8];
#pragma unroll
                for (int k = 0; k < 8; k++) acc[k] = 0.f;
#pragma unroll
                for (int d = 0; d < D_; d++) {
                    const float xd = (d < 4) ? ((const float*)&xa)[d] : ((const float*)&xb)[d - 4];
                    const float4* s4 = (const float4*)(S_s + (c * D_ + d) * 16);
                    const float4 s0 = s4[0], s1 = s4[1];
                    acc[0] += xd * s0.x; acc[1] += xd * s0.y; acc[2] += xd * s0.z; acc[3] += xd * s0.w;
                    acc[4] += xd * s1.x; acc[5] += xd * s1.y; acc[6] += xd * s1.z; acc[7] += xd * s1.w;
                }
#pragma unroll
                for (int k = 0; k < 8; k++)
                    if (acc[k] > T_s[c * K15_ + k]) m |= (1u << k);
            }
            {   // k = 8..14
                float acc[8];
#pragma unroll
                for (int k = 0; k < 8; k++) acc[k] = 0.f;
#pragma unroll
                for (int d = 0; d < D_; d++) {
                    const float xd = (d < 4) ? ((const float*)&xa)[d] : ((const float*)&xb)[d - 4];
                    const float4* s4 = (const float4*)(S_s + (c * D_ + d) * 16);
                    const float4 s2 = s4[2], s3 = s4[3];
                    acc[0] += xd * s2.x; acc[1] += xd * s2.y; acc[2] += xd * s2.z; acc[3] += xd * s2.w;
                    acc[4] += xd * s3.x; acc[5] += xd * s3.y; acc[6] += xd * s3.z;
                }
#pragma unroll
                for (int k = 0; k < 7; k++)
                    if (acc[k] > T_s[c * K15_ + 8 + k]) m |= (1u << (8 + k));
            }
            e8[cc] = g_table[m];
        }

        if (b < B) {
            uint4 pk;
            pk.x = (uint32_t)(e8[0] << 7) | ((uint32_t)(e8[1] << 7) << 16);
            pk.y = (uint32_t)(e8[2] << 7) | ((uint32_t)(e8[3] << 7) << 16);
            pk.z = (uint32_t)(e8[4] << 7) | ((uint32_t)(e8[5] << 7) << 16);
            pk.w = (uint32_t)(e8[6] << 7) | ((uint32_t)(e8[7] << 7) << 16);
            *(uint4*)(g_poff + (size_t)b * C_ + cg * 8) = pk;
        }
        __threadfence();
        __syncthreads();
        if (tid == 0) atomicExch(&g_cflag[ch], 1u);   // publish chunk
    }

    // ================= stage C prologue: convert own jt tile (overlaps peers' idx)
    {
        const int seg = tid & 15;
#pragma unroll
        for (int it = 0; it < 16; it++) {
            const int row = (tid >> 4) + it * 64;
            const float4 a = __ldg((const float4*)(LUT + (size_t)row * OUTW + jt * 64 + seg * 4));
            __half2 h0 = __floats2half2_rn(a.x, a.y);
            __half2 h1 = __floats2half2_rn(a.z, a.w);
            uint2 v;
            v.x = *(uint32_t*)&h0; v.y = *(uint32_t*)&h1;
            *(uint2*)(smem + TOFF + (size_t)row * ROWB + seg * 8) = v;
        }
    }

    // ================= stage C: gather with per-chunk flag waits ============
    const int half = lane >> 4, l16 = lane & 15;
    const char* tile = smem + TOFF + l16 * 8;

    if (y >= nch) return;   // no chunks for this CTA (tiny B only)

    // first chunk: wait flag, load ids
    if (tid == 0) {
        while (*(volatile unsigned*)&g_cflag[y] == 0u) {}
        __threadfence();
    }
    __syncthreads();        // flag passed + tile stores done (all threads)
    {
        const unsigned char* ip = (const unsigned char*)g_poff + (size_t)y * GCH * 128;
        cp16(sb + IDB0 + tid * 16, ip + tid * 16);
        asm volatile("cp.async.commit_group;" ::: "memory");
        asm volatile("cp.async.wait_group 0;" ::: "memory");
    }
    __syncthreads();

    int ch = y;
    uint32_t bufo = IDB0;
    while (ch < nch) {
        const int nx = ch + GY;
        if (nx < nch) {   // wait + prefetch next chunk's ids into other buffer
            if (tid == 0) {
                while (*(volatile unsigned*)&g_cflag[nx] == 0u) {}
                __threadfence();
            }
            __syncthreads();
            const uint32_t nbo = bufo ^ (IDB0 ^ IDB1);
            const unsigned char* ip = (const unsigned char*)g_poff + (size_t)nx * GCH * 128;
            cp16(sb + nbo + tid * 16, ip + tid * 16);
            asm volatile("cp.async.commit_group;" ::: "memory");
        }

        const int bbase = ch * GCH;
#pragma unroll
        for (int i = 0; i < 2; i++) {
            const int bl = w * 4 + 2 * i + half;
            const uint4* idp = (const uint4*)(smem + bufo + bl * 128);
            float4 a = make_float4(0.f, 0.f, 0.f, 0.f);
#pragma unroll
            for (int c8 = 0; c8 < 8; c8++) {
                const uint4 id8 = idp[c8];                       // LDS.128 broadcast / half
                const uint32_t o0 = id8.x & 0xFFFFu, o1 = id8.x >> 16;
                const uint32_t o2 = id8.y & 0xFFFFu, o3 = id8.y >> 16;
                const uint32_t o4 = id8.z & 0xFFFFu, o5 = id8.z >> 16;
                const uint32_t o6 = id8.w & 0xFFFFu, o7 = id8.w >> 16;
                const char* cb = tile + (size_t)(c8 * 8) * 2048;
                const uint2 v0 = *(const uint2*)(cb + o0 + 0 * 2048);
                const uint2 v1 = *(const uint2*)(cb + o1 + 1 * 2048);
                const uint2 v2 = *(const uint2*)(cb + o2 + 2 * 2048);
                const uint2 v3 = *(const uint2*)(cb + o3 + 3 * 2048);
                const uint2 v4 = *(const uint2*)(cb + o4 + 4 * 2048);
                const uint2 v5 = *(const uint2*)(cb + o5 + 5 * 2048);
                const uint2 v6 = *(const uint2*)(cb + o6 + 6 * 2048);
                const uint2 v7 = *(const uint2*)(cb + o7 + 7 * 2048);
                {
                    __half2 s0 = __hadd2(__hadd2(*(const __half2*)&v0.x, *(const __half2*)&v1.x),
                                         __hadd2(*(const __half2*)&v2.x, *(const __half2*)&v3.x));
                    __half2 s1 = __hadd2(__hadd2(*(const __half2*)&v0.y, *(const __half2*)&v1.y),
                                         __hadd2(*(const __half2*)&v2.y, *(const __half2*)&v3.y));
                    const float2 f0 = __half22float2(s0);
                    const float2 f1 = __half22float2(s1);
                    a.x += f0.x; a.y += f0.y; a.z += f1.x; a.w += f1.y;
                }
                {
                    __half2 s0 = __hadd2(__hadd2(*(const __half2*)&v4.x, *(const __half2*)&v5.x),
                                         __hadd2(*(const __half2*)&v6.x, *(const __half2*)&v7.x));
                    __half2 s1 = __hadd2(__hadd2(*(const __half2*)&v4.y, *(const __half2*)&v5.y),
                                         __hadd2(*(const __half2*)&v6.y, *(const __half2*)&v7.y));
                    const float2 f0 = __half22float2(s0);
                    const float2 f1 = __half22float2(s1);
                    a.x += f0.x; a.y += f0.y; a.z += f1.x; a.w += f1.y;
                }
            }
            const int b = bbase + bl;
            if (b < B)
                *(float4*)(out + (size_t)b * OUTW + jt * 64 + l16 * 4) = a;
        }

        // consume-mark ch (8 consumers; 8th resets flag for next graph replay)
        if (tid == 0) {
            const unsigned old = atomicAdd(&g_cdone[ch], 1u);
            if (old == 7u) { g_cdone[ch] = 0u; g_cflag[ch] = 0u; }
        }

        if (nx >= nch) break;
        asm volatile("cp.async.wait_group 0;" ::: "memory");
        __syncthreads();     // old buffer drained + new ids visible
        bufo ^= (IDB0 ^ IDB1);
        ch = nx;
    }
}

// ---------------------------------------------------------------------------
extern "C" void kernel_launch(void* const* d_in, const int* in_sizes, int n_in,
                              void* d_out, int out_size) {
    const float* x   = (const float*)d_in[0];
    const float* S   = (const float*)d_in[1];
    const float* H   = (const float*)d_in[2];
    const float* T   = (const float*)d_in[3];
    const float* LUT = (const float*)d_in[4];
    float*       out = (float*)d_out;

    const int B = in_sizes[0] / (C_ * D_);

    cudaFuncSetAttribute(fused_kernel, cudaFuncAttributeMaxDynamicSharedMemorySize, GSMEM);
    fused_kernel<<<NCTA, 1024, GSMEM>>>(x, S, T, H, LUT, out, B);
}